// round 6
// baseline (speedup 1.0000x reference)
#include <cuda_runtime.h>

// Detail_loss: loss = (mean|conv(dx,kh)| + mean|conv(dx,kv)|)/2, dx=infer-ref,
// fixed [-0.5,0,0.5] kernels broadcast over 3x3 channel pairs.
// Reduces to S = sum_c(infer-ref); accumulate |S[h,w+1]-S[h,w-1]| + |S[h+1,w]-S[h-1,w]|
// (zero pad), scaled by 1/(4 * N * 258 * 256).
//
// Smem-free streaming: each warp owns an 8-row x 128-col strip (64 strips/img,
// 784 blocks -> ~42 warps/SM). Rolling 3-row float4 register window for vertical
// grads; warp shuffles + scalar halo loads for horizontal. Fully unrolled row
// loop for front-batched LDG.128. Single kernel, atomic finalize.

#define H 256
#define W 256
#define C 3
#define RSTRIP 8
#define IMG (C * H * W)

__device__ double       g_acc   = 0.0;
__device__ unsigned int g_count = 0;

__device__ __forceinline__ float4 loadS4(const float* __restrict__ pi,
                                         const float* __restrict__ pr, int r) {
    const size_t ro = (size_t)r * W;
    float4 v = make_float4(0.f, 0.f, 0.f, 0.f);
    #pragma unroll
    for (int ch = 0; ch < C; ch++) {
        const size_t o = ro + (size_t)ch * (H * W);
        const float4 a = __ldg((const float4*)(pi + o));
        const float4 b = __ldg((const float4*)(pr + o));
        v.x += a.x - b.x; v.y += a.y - b.y;
        v.z += a.z - b.z; v.w += a.w - b.w;
    }
    return v;
}

__device__ __forceinline__ float loadS1(const float* __restrict__ pi,
                                        const float* __restrict__ pr, int r) {
    const size_t ro = (size_t)r * W;
    float v = 0.f;
    #pragma unroll
    for (int ch = 0; ch < C; ch++) {
        const size_t o = ro + (size_t)ch * (H * W);
        v += __ldg(pi + o) - __ldg(pr + o);
    }
    return v;
}

__global__ __launch_bounds__(256)
void dl_fused(const float* __restrict__ infer, const float* __restrict__ ref,
              float* __restrict__ out, int n_img)
{
    const int tid  = threadIdx.x;
    const int lane = tid & 31;
    const int wid  = tid >> 5;
    const int gw   = blockIdx.x * 8 + wid;   // global warp id = strip id
    const int n    = gw >> 6;                // image (64 strips per image)
    const int rem  = gw & 63;
    const int seg  = rem & 1;                // column segment 0/1
    const int rs   = rem >> 1;               // row strip 0..31
    const int r0   = rs * RSTRIP;
    const int c0   = seg * 128;
    const int col  = c0 + lane * 4;

    const float* pi = infer + (size_t)n * IMG + col;
    const float* pr = ref   + (size_t)n * IMG + col;

    // Halo column: lane 0 needs S[.,c0-1]; lane 31 needs S[.,c0+128].
    const bool wantHalo = (lane == 0) ? (c0 > 0)
                        : ((lane == 31) && (c0 + 128 < W));
    const int hoff = ((lane == 0) ? -1 : 128) - lane * 4;  // relative to col
    const float* hi = pi + hoff;
    const float* hr = pr + hoff;

    float4 a  = (r0 > 0) ? loadS4(pi, pr, r0 - 1) : make_float4(0.f, 0.f, 0.f, 0.f);
    float4 b  = loadS4(pi, pr, r0);
    float  bh = wantHalo ? loadS1(hi, hr, r0) : 0.f;

    float acc = 0.f;
    #pragma unroll
    for (int i = 0; i < RSTRIP; i++) {
        const int r = r0 + i;
        float4 c   = make_float4(0.f, 0.f, 0.f, 0.f);
        float  chv = 0.f;
        if (r + 1 < H) {                       // uniform per warp (last strip only)
            c = loadS4(pi, pr, r + 1);
            if (wantHalo) chv = loadS1(hi, hr, r + 1);
        }
        // horizontal gradients of row r (factor-2 grads; scaled at the end)
        float lf = __shfl_up_sync(0xffffffffu, b.w, 1);
        float rt = __shfl_down_sync(0xffffffffu, b.x, 1);
        if (lane == 0)  lf = bh;   // left halo (0 at image edge)
        if (lane == 31) rt = bh;   // right halo (0 at image edge)
        acc += fabsf(b.y - lf) + fabsf(b.z - b.x)
             + fabsf(b.w - b.y) + fabsf(rt  - b.z);
        // vertical gradients of row r
        acc += fabsf(c.x - a.x) + fabsf(c.y - a.y)
             + fabsf(c.z - a.z) + fabsf(c.w - a.w);
        a = b; b = c; bh = chv;
    }

    // ---- warp + block reduction ----
    #pragma unroll
    for (int o = 16; o; o >>= 1) acc += __shfl_down_sync(0xffffffffu, acc, o);
    __shared__ float wsum[8];
    if (lane == 0) wsum[wid] = acc;
    __syncthreads();
    if (tid == 0) {
        float t = 0.f;
        #pragma unroll
        for (int i = 0; i < 8; i++) t += wsum[i];
        atomicAdd(&g_acc, (double)t);
        __threadfence();
        const unsigned old = atomicAdd(&g_count, 1u);
        if (old == gridDim.x - 1u) {            // last block finalizes
            __threadfence();
            const double s = atomicAdd(&g_acc, 0.0);  // coherent read
            out[0] = (float)(s / (4.0 * (double)n_img * 258.0 * 256.0));
            g_acc   = 0.0;                      // reset for next graph replay
            g_count = 0u;
        }
    }
}

extern "C" void kernel_launch(void* const* d_in, const int* in_sizes, int n_in,
                              void* d_out, int out_size) {
    const float* infer = (const float*)d_in[0];
    const float* ref   = (const float*)d_in[1];
    const int n_img = in_sizes[0] / IMG;               // 2*7*7 = 98
    const int nblk  = n_img * 64 / 8;                  // 784
    dl_fused<<<nblk, 256>>>(infer, ref, (float*)d_out, n_img);
}

// round 7
// speedup vs baseline: 1.0402x; 1.0402x over previous
#include <cuda_runtime.h>

// Detail_loss: loss = (mean|conv(dx,kh)| + mean|conv(dx,kv)|)/2, dx=infer-ref,
// fixed [-0.5,0,0.5] kernels broadcast over 3x3 channel pairs.
// Reduces to S = sum_c(infer-ref); accumulate |S[h,w+1]-S[h,w-1]| + |S[h+1,w]-S[h-1,w]|
// (zero pad), scaled by 1/(4 * N * 258 * 256).
//
// Smem-free streaming: each warp owns an 8-row x 128-col strip (64 strips/img,
// 784 blocks -> ~42 warps/SM). Rolling 3-row float4 register window for vertical
// grads; warp shuffles + scalar halo loads for horizontal. Fully unrolled row
// loop for front-batched LDG.128. Single kernel, atomic finalize.

#define H 256
#define W 256
#define C 3
#define RSTRIP 8
#define IMG (C * H * W)

__device__ double       g_acc   = 0.0;
__device__ unsigned int g_count = 0;

__device__ __forceinline__ float4 loadS4(const float* __restrict__ pi,
                                         const float* __restrict__ pr, int r) {
    const size_t ro = (size_t)r * W;
    float4 v = make_float4(0.f, 0.f, 0.f, 0.f);
    #pragma unroll
    for (int ch = 0; ch < C; ch++) {
        const size_t o = ro + (size_t)ch * (H * W);
        const float4 a = __ldg((const float4*)(pi + o));
        const float4 b = __ldg((const float4*)(pr + o));
        v.x += a.x - b.x; v.y += a.y - b.y;
        v.z += a.z - b.z; v.w += a.w - b.w;
    }
    return v;
}

__device__ __forceinline__ float loadS1(const float* __restrict__ pi,
                                        const float* __restrict__ pr, int r) {
    const size_t ro = (size_t)r * W;
    float v = 0.f;
    #pragma unroll
    for (int ch = 0; ch < C; ch++) {
        const size_t o = ro + (size_t)ch * (H * W);
        v += __ldg(pi + o) - __ldg(pr + o);
    }
    return v;
}

__global__ __launch_bounds__(256)
void dl_fused(const float* __restrict__ infer, const float* __restrict__ ref,
              float* __restrict__ out, int n_img)
{
    const int tid  = threadIdx.x;
    const int lane = tid & 31;
    const int wid  = tid >> 5;
    const int gw   = blockIdx.x * 8 + wid;   // global warp id = strip id
    const int n    = gw >> 6;                // image (64 strips per image)
    const int rem  = gw & 63;
    const int seg  = rem & 1;                // column segment 0/1
    const int rs   = rem >> 1;               // row strip 0..31
    const int r0   = rs * RSTRIP;
    const int c0   = seg * 128;
    const int col  = c0 + lane * 4;

    const float* pi = infer + (size_t)n * IMG + col;
    const float* pr = ref   + (size_t)n * IMG + col;

    // Halo column: lane 0 needs S[.,c0-1]; lane 31 needs S[.,c0+128].
    const bool wantHalo = (lane == 0) ? (c0 > 0)
                        : ((lane == 31) && (c0 + 128 < W));
    const int hoff = ((lane == 0) ? -1 : 128) - lane * 4;  // relative to col
    const float* hi = pi + hoff;
    const float* hr = pr + hoff;

    float4 a  = (r0 > 0) ? loadS4(pi, pr, r0 - 1) : make_float4(0.f, 0.f, 0.f, 0.f);
    float4 b  = loadS4(pi, pr, r0);
    float  bh = wantHalo ? loadS1(hi, hr, r0) : 0.f;

    float acc = 0.f;
    #pragma unroll
    for (int i = 0; i < RSTRIP; i++) {
        const int r = r0 + i;
        float4 c   = make_float4(0.f, 0.f, 0.f, 0.f);
        float  chv = 0.f;
        if (r + 1 < H) {                       // uniform per warp (last strip only)
            c = loadS4(pi, pr, r + 1);
            if (wantHalo) chv = loadS1(hi, hr, r + 1);
        }
        // horizontal gradients of row r (factor-2 grads; scaled at the end)
        float lf = __shfl_up_sync(0xffffffffu, b.w, 1);
        float rt = __shfl_down_sync(0xffffffffu, b.x, 1);
        if (lane == 0)  lf = bh;   // left halo (0 at image edge)
        if (lane == 31) rt = bh;   // right halo (0 at image edge)
        acc += fabsf(b.y - lf) + fabsf(b.z - b.x)
             + fabsf(b.w - b.y) + fabsf(rt  - b.z);
        // vertical gradients of row r
        acc += fabsf(c.x - a.x) + fabsf(c.y - a.y)
             + fabsf(c.z - a.z) + fabsf(c.w - a.w);
        a = b; b = c; bh = chv;
    }

    // ---- warp + block reduction ----
    #pragma unroll
    for (int o = 16; o; o >>= 1) acc += __shfl_down_sync(0xffffffffu, acc, o);
    __shared__ float wsum[8];
    if (lane == 0) wsum[wid] = acc;
    __syncthreads();
    if (tid == 0) {
        float t = 0.f;
        #pragma unroll
        for (int i = 0; i < 8; i++) t += wsum[i];
        atomicAdd(&g_acc, (double)t);
        __threadfence();
        const unsigned old = atomicAdd(&g_count, 1u);
        if (old == gridDim.x - 1u) {            // last block finalizes
            __threadfence();
            const double s = atomicAdd(&g_acc, 0.0);  // coherent read
            out[0] = (float)(s / (4.0 * (double)n_img * 258.0 * 256.0));
            g_acc   = 0.0;                      // reset for next graph replay
            g_count = 0u;
        }
    }
}

extern "C" void kernel_launch(void* const* d_in, const int* in_sizes, int n_in,
                              void* d_out, int out_size) {
    const float* infer = (const float*)d_in[0];
    const float* ref   = (const float*)d_in[1];
    const int n_img = in_sizes[0] / IMG;               // 2*7*7 = 98
    const int nblk  = n_img * 64 / 8;                  // 784
    dl_fused<<<nblk, 256>>>(infer, ref, (float*)d_out, n_img);
}